// round 9
// baseline (speedup 1.0000x reference)
#include <cuda_runtime.h>
#include <cstdint>

// Log-signature depth 3, d=8, L=256, B=2048.
// R7: R6 structure (smem-staged dx, packed f32x2 scan, Chen tree-combine,
// aliased smem) + launch_bounds(256,4): <=64 regs, 4 blocks/SM, 32 warps/SM,
// and grid 512 <= capacity 592 -> the entire kernel runs in ONE wave (no
// tail). Scan unroll reduced to 2 to keep load-prefetch register pressure
// inside the 64-reg budget.

#define BATCH   2048
#define LPATH   256
#define DCH     8
#define OUT_PB  584
#define TPB     256            // 16 groups = 4 batches x 4 chunks
#define BPB     4
#define SIGSZ   656            // 8 + 8x9 (S2) + 64x9 (S3)
#define DXS     2052           // floats per batch dx region (8*256 + 4 pad)
#define SMEMF   10496          // max(4*DXS=8208, 16*SIGSZ=10496)

using u64 = unsigned long long;

__device__ __forceinline__ u64 pack2(float lo, float hi) {
    u64 r; asm("mov.b64 %0, {%1, %2};" : "=l"(r) : "f"(lo), "f"(hi)); return r;
}
__device__ __forceinline__ void unpack2(u64 v, float& lo, float& hi) {
    asm("mov.b64 {%0, %1}, %2;" : "=f"(lo), "=f"(hi) : "l"(v));
}
__device__ __forceinline__ u64 fma2(u64 a, u64 b, u64 c) {
    u64 d; asm("fma.rn.f32x2 %0, %1, %2, %3;" : "=l"(d) : "l"(a), "l"(b), "l"(c)); return d;
}

__global__ __launch_bounds__(TPB, 4)
void logsig_kernel(const float* __restrict__ x, float* __restrict__ out)
{
    __shared__ __align__(16) float smem[SMEMF];

    const int tid  = threadIdx.x;
    const int lane = tid & 31;
    const int s    = lane & 15;
    const int i    = s >> 1;
    const bool hib = (s & 1) != 0;
    const int jb   = hib ? 4 : 0;

    const int gid   = tid >> 4;
    const int bL    = gid >> 2;
    const int chunk = gid & 3;
    const long b = (long)blockIdx.x * BPB + bL;
    const int start = chunk * 64;

    // ---------------- phase 1: dx -> shared (padded, dx[255]=0) ----------
    {
        const float4* xg = reinterpret_cast<const float4*>(
            x + (size_t)blockIdx.x * BPB * LPATH * DCH);
#pragma unroll 2
        for (int k = 0; k < 8; ++k) {
            int e  = tid + 256 * k;        // 0..2047 : (batch, point, half)
            int bb = e >> 9;
            int r  = e & 511;
            int t  = r >> 1;
            int h  = r & 1;
            int tn = (t < 255) ? t + 1 : 255;     // pad point -> dx = 0
            const float4* xb4 = xg + bb * 512;
            float4 cur = __ldg(xb4 + 2 * t  + h);
            float4 nxt = __ldg(xb4 + 2 * tn + h);
            float4 dv;
            dv.x = nxt.x - cur.x; dv.y = nxt.y - cur.y;
            dv.z = nxt.z - cur.z; dv.w = nxt.w - cur.w;
            *reinterpret_cast<float4*>(&smem[bb * DXS + t * 8 + h * 4]) = dv;
        }
    }
    __syncthreads();

    // ---------------- phase 2: 64-step packed scan from smem -------------
    u64 S3p[4][4];
#pragma unroll
    for (int q = 0; q < 4; ++q)
#pragma unroll
        for (int kp = 0; kp < 4; ++kp) S3p[q][kp] = 0ull;
    u64 S2p0 = 0ull, S2p1 = 0ull;
    float S1i = 0.0f;

    const float* dxp = &smem[bL * DXS + start * 8];
    const longlong2* dv2 = reinterpret_cast<const longlong2*>(dxp);

#pragma unroll 2
    for (int t = 0; t < 64; ++t) {
        longlong2 va = dv2[2 * t];
        longlong2 vb = dv2[2 * t + 1];
        float dxi = dxp[t * 8 + i];

        u64 d0 = (u64)va.x, d1 = (u64)va.y, d2 = (u64)vb.x, d3 = (u64)vb.y;

        float av = fmaf(dxi, 1.0f / 6.0f, 0.5f * S1i);   // old S1i
        float bv = fmaf(dxi, 0.5f, S1i);
        S1i += dxi;
        u64 a2 = pack2(av, av);
        u64 b2 = pack2(bv, bv);

        u64 dj01 = hib ? d2 : d0;
        u64 dj23 = hib ? d3 : d1;

        u64 m01 = fma2(a2, dj01, S2p0);                  // old S2
        u64 m23 = fma2(a2, dj23, S2p1);
        S2p0 = fma2(b2, dj01, S2p0);
        S2p1 = fma2(b2, dj23, S2p1);

        float m0, m1, m2, m3;
        unpack2(m01, m0, m1); unpack2(m23, m2, m3);
        u64 M0 = pack2(m0, m0), M1 = pack2(m1, m1);
        u64 M2 = pack2(m2, m2), M3 = pack2(m3, m3);

        S3p[0][0] = fma2(M0, d0, S3p[0][0]);
        S3p[0][1] = fma2(M0, d1, S3p[0][1]);
        S3p[0][2] = fma2(M0, d2, S3p[0][2]);
        S3p[0][3] = fma2(M0, d3, S3p[0][3]);
        S3p[1][0] = fma2(M1, d0, S3p[1][0]);
        S3p[1][1] = fma2(M1, d1, S3p[1][1]);
        S3p[1][2] = fma2(M1, d2, S3p[1][2]);
        S3p[1][3] = fma2(M1, d3, S3p[1][3]);
        S3p[2][0] = fma2(M2, d0, S3p[2][0]);
        S3p[2][1] = fma2(M2, d1, S3p[2][1]);
        S3p[2][2] = fma2(M2, d2, S3p[2][2]);
        S3p[2][3] = fma2(M2, d3, S3p[2][3]);
        S3p[3][0] = fma2(M3, d0, S3p[3][0]);
        S3p[3][1] = fma2(M3, d1, S3p[3][1]);
        S3p[3][2] = fma2(M3, d2, S3p[3][2]);
        S3p[3][3] = fma2(M3, d3, S3p[3][3]);
    }

    // ---- unpack scan state; S1 via telescoped endpoints (GMEM, L2-hot) --
    float S3f[4][8];
#pragma unroll
    for (int q = 0; q < 4; ++q)
#pragma unroll
        for (int kp = 0; kp < 4; ++kp)
            unpack2(S3p[q][kp], S3f[q][2 * kp], S3f[q][2 * kp + 1]);
    float S2f[4];
    unpack2(S2p0, S2f[0], S2f[1]);
    unpack2(S2p1, S2f[2], S2f[3]);

    float S1f[8];
    {
        const float4* xg2 = reinterpret_cast<const float4*>(
            x + (size_t)b * LPATH * DCH);
        int pend = (chunk == 3) ? 255 : (start + 64);
        float4 e0 = __ldg(xg2 + 2 * pend);
        float4 e1 = __ldg(xg2 + 2 * pend + 1);
        float4 s0 = __ldg(xg2 + 2 * start);
        float4 s1 = __ldg(xg2 + 2 * start + 1);
        S1f[0] = e0.x - s0.x; S1f[1] = e0.y - s0.y;
        S1f[2] = e0.z - s0.z; S1f[3] = e0.w - s0.w;
        S1f[4] = e1.x - s1.x; S1f[5] = e1.y - s1.y;
        S1f[6] = e1.z - s1.z; S1f[7] = e1.w - s1.w;
    }

    // ---------------- Chen tree-combine (smem aliased over dx) -----------
    __syncthreads();                       // dx buffer is dead from here on
    float (*sig)[SIGSZ] = reinterpret_cast<float (*)[SIGSZ]>(smem);

    auto store_sig = [&](float* p) {
        if (s == 0) {
#pragma unroll
            for (int k = 0; k < 8; ++k) p[k] = S1f[k];
        }
#pragma unroll
        for (int q = 0; q < 4; ++q)
            p[8 + i * 9 + jb + q] = S2f[q];
#pragma unroll
        for (int q = 0; q < 4; ++q)
#pragma unroll
            for (int k = 0; k < 8; ++k)
                p[80 + (i * 8 + jb + q) * 9 + k] = S3f[q][k];
    };

    auto combine = [&](const float* p) {   // regs = earlier part a, p = later part b
        float S1b[8];
#pragma unroll
        for (int k = 0; k < 8; ++k) S1b[k] = p[k];
#pragma unroll
        for (int q = 0; q < 4; ++q) {
            const float* s2row = p + 8 + (jb + q) * 9;            // S2b[j,:]
            const float* s3row = p + 80 + (i * 8 + jb + q) * 9;   // S3b[i,j,:]
#pragma unroll
            for (int k = 0; k < 8; ++k)
                S3f[q][k] += S2f[q] * S1b[k] + S1i * s2row[k] + s3row[k];
            float S1bj = hib ? S1b[4 + q] : S1b[q];
            S2f[q] += S1i * S1bj + p[8 + i * 9 + jb + q];
        }
#pragma unroll
        for (int k = 0; k < 8; ++k) S1f[k] += S1b[k];
        S1i += p[i];
    };

    if (chunk == 1 || chunk == 3) store_sig(&sig[bL * 4 + chunk][0]);
    __syncthreads();
    if (chunk == 0) {
        combine(&sig[bL * 4 + 1][0]);
    } else if (chunk == 2) {
        combine(&sig[bL * 4 + 3][0]);
        store_sig(&sig[bL * 4 + 2][0]);
    }
    __syncthreads();
    if (chunk != 0) return;          // chunk-0 groups are always lanes 0-15

    combine(&sig[bL * 4 + 2][0]);

    // ---------------- log projection + writeback ----------------
    float* p0 = &sig[bL * 4 + 0][0];
#pragma unroll
    for (int q = 0; q < 4; ++q)
        p0[8 + i * 9 + jb + q] = S2f[q];   // publish full S2 for [j,k] reads
    __syncwarp(0x0000FFFFu);

    float* ob = out + (size_t)b * OUT_PB;

    // l1
    if (s == 0) {
        *reinterpret_cast<float4*>(ob)     = make_float4(S1f[0], S1f[1], S1f[2], S1f[3]);
        *reinterpret_cast<float4*>(ob + 4) = make_float4(S1f[4], S1f[5], S1f[6], S1f[7]);
    }

    // l2 = S2 - 0.5 S1 x S1
    {
        float4 v; float* vv = &v.x;
#pragma unroll
        for (int q = 0; q < 4; ++q) {
            float S1j = hib ? S1f[4 + q] : S1f[q];
            vv[q] = S2f[q] - 0.5f * S1i * S1j;
        }
        *reinterpret_cast<float4*>(ob + 8 + 4 * s) = v;
    }

    // l3 = S3 - 0.5 (S1_i S2[j,k] + S2[i,j] S1_k) + (1/3) S1_i S1_j S1_k
#pragma unroll
    for (int q = 0; q < 4; ++q) {
        float S1j  = hib ? S1f[4 + q] : S1f[q];
        float S2ij = S2f[q];
        float tij  = (1.0f / 3.0f) * S1i * S1j;
        const float* row = p0 + 8 + (jb + q) * 9;    // S2[j,:]
        float4 lo, hi4;
        float* lv = &lo.x; float* hv = &hi4.x;
#pragma unroll
        for (int k = 0; k < 8; ++k) {
            float val = S3f[q][k]
                      - 0.5f * (S1i * row[k] + S2ij * S1f[k])
                      + tij * S1f[k];
            if (k < 4) lv[k] = val; else hv[k - 4] = val;
        }
        float* dst = ob + 72 + 32 * s + 8 * q;
        *reinterpret_cast<float4*>(dst)     = lo;
        *reinterpret_cast<float4*>(dst + 4) = hi4;
    }
}

extern "C" void kernel_launch(void* const* d_in, const int* in_sizes, int n_in,
                              void* d_out, int out_size)
{
    const float* x = (const float*)d_in[0];
    float* out = (float*)d_out;
    (void)in_sizes; (void)n_in; (void)out_size;

    const int blocks = BATCH / BPB;   // 512
    logsig_kernel<<<blocks, TPB>>>(x, out);
}

// round 11
// speedup vs baseline: 1.1617x; 1.1617x over previous
#include <cuda_runtime.h>
#include <cstdint>

// Log-signature depth 3, d=8, L=256, B=2048.
// R9: R6 structure (smem-staged dx, packed f32x2 scan, Chen combine, aliased
// smem) re-chunked 4 -> 3 chunks/path (255 = 3*85 exactly). Total warps
// 3072 <= chip residency 3552 @80regs -> ONE wave, no tail. Block = 192
// threads (4 batches x 3 chunks), launch_bounds(192,4).

#define BATCH   2048
#define LPATH   256
#define DCH     8
#define OUT_PB  584
#define TPB     192            // 12 groups = 4 batches x 3 chunks
#define BPB     4
#define NCHUNK  3
#define CSTEPS  85             // 255 / 3
#define SIGSZ   656            // 8 + 8x9 (S2) + 64x9 (S3)
#define DXS     2052           // floats per batch dx region (8*256 + 4 pad)
#define SMEMF   8208           // 4*DXS; >= 12*SIGSZ = 7872 (sig aliases dx)

using u64 = unsigned long long;

__device__ __forceinline__ u64 pack2(float lo, float hi) {
    u64 r; asm("mov.b64 %0, {%1, %2};" : "=l"(r) : "f"(lo), "f"(hi)); return r;
}
__device__ __forceinline__ void unpack2(u64 v, float& lo, float& hi) {
    asm("mov.b64 {%0, %1}, %2;" : "=f"(lo), "=f"(hi) : "l"(v));
}
__device__ __forceinline__ u64 fma2(u64 a, u64 b, u64 c) {
    u64 d; asm("fma.rn.f32x2 %0, %1, %2, %3;" : "=l"(d) : "l"(a), "l"(b), "l"(c)); return d;
}

__global__ __launch_bounds__(TPB, 4)
void logsig_kernel(const float* __restrict__ x, float* __restrict__ out)
{
    __shared__ __align__(16) float smem[SMEMF];

    const int tid  = threadIdx.x;
    const int lane = tid & 31;
    const int s    = lane & 15;
    const int i    = s >> 1;
    const bool hib = (s & 1) != 0;
    const int jb   = hib ? 4 : 0;
    const unsigned gmask = 0xFFFFu << (lane & 16);

    const int gid   = tid >> 4;        // 0..11
    const int bL    = gid / NCHUNK;    // batch within block
    const int chunk = gid - bL * NCHUNK;
    const long b = (long)blockIdx.x * BPB + bL;
    const int start = chunk * CSTEPS;

    // ---------------- phase 1: dx -> shared ----------------
    {
        const float4* xg = reinterpret_cast<const float4*>(
            x + (size_t)blockIdx.x * BPB * LPATH * DCH);
#pragma unroll
        for (int k = 0; k < 11; ++k) {
            int e = tid + TPB * k;          // (batch, point, half) in float4 units
            if (e < 2048) {
                int bb = e >> 9;
                int r  = e & 511;
                int t  = r >> 1;
                int h  = r & 1;
                int tn = (t < 255) ? t + 1 : 255;   // dx[255] never read
                const float4* xb4 = xg + bb * 512;
                float4 cur = __ldg(xb4 + 2 * t  + h);
                float4 nxt = __ldg(xb4 + 2 * tn + h);
                float4 dv;
                dv.x = nxt.x - cur.x; dv.y = nxt.y - cur.y;
                dv.z = nxt.z - cur.z; dv.w = nxt.w - cur.w;
                *reinterpret_cast<float4*>(&smem[bb * DXS + t * 8 + h * 4]) = dv;
            }
        }
    }
    __syncthreads();

    // ---------------- phase 2: 85-step packed scan from smem -------------
    u64 S3p[4][4];
#pragma unroll
    for (int q = 0; q < 4; ++q)
#pragma unroll
        for (int kp = 0; kp < 4; ++kp) S3p[q][kp] = 0ull;
    u64 S2p0 = 0ull, S2p1 = 0ull;
    float S1i = 0.0f;

    const float* dxp = &smem[bL * DXS + start * 8];
    const longlong2* dv2 = reinterpret_cast<const longlong2*>(dxp);

#pragma unroll 4
    for (int t = 0; t < CSTEPS; ++t) {
        longlong2 va = dv2[2 * t];
        longlong2 vb = dv2[2 * t + 1];
        float dxi = dxp[t * 8 + i];

        u64 d0 = (u64)va.x, d1 = (u64)va.y, d2 = (u64)vb.x, d3 = (u64)vb.y;

        float av = fmaf(dxi, 1.0f / 6.0f, 0.5f * S1i);   // old S1i
        float bv = fmaf(dxi, 0.5f, S1i);
        S1i += dxi;
        u64 a2 = pack2(av, av);
        u64 b2 = pack2(bv, bv);

        u64 dj01 = hib ? d2 : d0;
        u64 dj23 = hib ? d3 : d1;

        u64 m01 = fma2(a2, dj01, S2p0);                  // old S2
        u64 m23 = fma2(a2, dj23, S2p1);
        S2p0 = fma2(b2, dj01, S2p0);
        S2p1 = fma2(b2, dj23, S2p1);

        float m0, m1, m2, m3;
        unpack2(m01, m0, m1); unpack2(m23, m2, m3);
        u64 M0 = pack2(m0, m0), M1 = pack2(m1, m1);
        u64 M2 = pack2(m2, m2), M3 = pack2(m3, m3);

        S3p[0][0] = fma2(M0, d0, S3p[0][0]);
        S3p[0][1] = fma2(M0, d1, S3p[0][1]);
        S3p[0][2] = fma2(M0, d2, S3p[0][2]);
        S3p[0][3] = fma2(M0, d3, S3p[0][3]);
        S3p[1][0] = fma2(M1, d0, S3p[1][0]);
        S3p[1][1] = fma2(M1, d1, S3p[1][1]);
        S3p[1][2] = fma2(M1, d2, S3p[1][2]);
        S3p[1][3] = fma2(M1, d3, S3p[1][3]);
        S3p[2][0] = fma2(M2, d0, S3p[2][0]);
        S3p[2][1] = fma2(M2, d1, S3p[2][1]);
        S3p[2][2] = fma2(M2, d2, S3p[2][2]);
        S3p[2][3] = fma2(M2, d3, S3p[2][3]);
        S3p[3][0] = fma2(M3, d0, S3p[3][0]);
        S3p[3][1] = fma2(M3, d1, S3p[3][1]);
        S3p[3][2] = fma2(M3, d2, S3p[3][2]);
        S3p[3][3] = fma2(M3, d3, S3p[3][3]);
    }

    // ---- unpack scan state; S1 via telescoped endpoints (GMEM, L2-hot) --
    float S3f[4][8];
#pragma unroll
    for (int q = 0; q < 4; ++q)
#pragma unroll
        for (int kp = 0; kp < 4; ++kp)
            unpack2(S3p[q][kp], S3f[q][2 * kp], S3f[q][2 * kp + 1]);
    float S2f[4];
    unpack2(S2p0, S2f[0], S2f[1]);
    unpack2(S2p1, S2f[2], S2f[3]);

    float S1f[8];
    {
        const float4* xg2 = reinterpret_cast<const float4*>(
            x + (size_t)b * LPATH * DCH);
        int pend = start + CSTEPS;        // 85 / 170 / 255 — always in range
        float4 e0 = __ldg(xg2 + 2 * pend);
        float4 e1 = __ldg(xg2 + 2 * pend + 1);
        float4 s0 = __ldg(xg2 + 2 * start);
        float4 s1 = __ldg(xg2 + 2 * start + 1);
        S1f[0] = e0.x - s0.x; S1f[1] = e0.y - s0.y;
        S1f[2] = e0.z - s0.z; S1f[3] = e0.w - s0.w;
        S1f[4] = e1.x - s1.x; S1f[5] = e1.y - s1.y;
        S1f[6] = e1.z - s1.z; S1f[7] = e1.w - s1.w;
    }

    // ---------------- Chen combine (smem aliased over dx) ----------------
    __syncthreads();                       // dx buffer dead from here on
    float (*sig)[SIGSZ] = reinterpret_cast<float (*)[SIGSZ]>(smem);

    auto store_sig = [&](float* p) {
        if (s == 0) {
#pragma unroll
            for (int k = 0; k < 8; ++k) p[k] = S1f[k];
        }
#pragma unroll
        for (int q = 0; q < 4; ++q)
            p[8 + i * 9 + jb + q] = S2f[q];
#pragma unroll
        for (int q = 0; q < 4; ++q)
#pragma unroll
            for (int k = 0; k < 8; ++k)
                p[80 + (i * 8 + jb + q) * 9 + k] = S3f[q][k];
    };

    auto combine = [&](const float* p) {   // regs = earlier part a, p = later part b
        float S1b[8];
#pragma unroll
        for (int k = 0; k < 8; ++k) S1b[k] = p[k];
#pragma unroll
        for (int q = 0; q < 4; ++q) {
            const float* s2row = p + 8 + (jb + q) * 9;            // S2b[j,:]
            const float* s3row = p + 80 + (i * 8 + jb + q) * 9;   // S3b[i,j,:]
#pragma unroll
            for (int k = 0; k < 8; ++k)
                S3f[q][k] += S2f[q] * S1b[k] + S1i * s2row[k] + s3row[k];
            float S1bj = hib ? S1b[4 + q] : S1b[q];
            S2f[q] += S1i * S1bj + p[8 + i * 9 + jb + q];
        }
#pragma unroll
        for (int k = 0; k < 8; ++k) S1f[k] += S1b[k];
        S1i += p[i];
    };

    if (chunk != 0) store_sig(&sig[bL * NCHUNK + chunk][0]);
    __syncthreads();
    if (chunk != 0) return;

    combine(&sig[bL * NCHUNK + 1][0]);
    combine(&sig[bL * NCHUNK + 2][0]);

    // ---------------- log projection + writeback ----------------
    float* p0 = &sig[bL * NCHUNK + 0][0];
#pragma unroll
    for (int q = 0; q < 4; ++q)
        p0[8 + i * 9 + jb + q] = S2f[q];   // publish full S2 for [j,k] reads
    __syncwarp(gmask);

    float* ob = out + (size_t)b * OUT_PB;

    // l1
    if (s == 0) {
        *reinterpret_cast<float4*>(ob)     = make_float4(S1f[0], S1f[1], S1f[2], S1f[3]);
        *reinterpret_cast<float4*>(ob + 4) = make_float4(S1f[4], S1f[5], S1f[6], S1f[7]);
    }

    // l2 = S2 - 0.5 S1 x S1
    {
        float4 v; float* vv = &v.x;
#pragma unroll
        for (int q = 0; q < 4; ++q) {
            float S1j = hib ? S1f[4 + q] : S1f[q];
            vv[q] = S2f[q] - 0.5f * S1i * S1j;
        }
        *reinterpret_cast<float4*>(ob + 8 + 4 * s) = v;
    }

    // l3 = S3 - 0.5 (S1_i S2[j,k] + S2[i,j] S1_k) + (1/3) S1_i S1_j S1_k
#pragma unroll
    for (int q = 0; q < 4; ++q) {
        float S1j  = hib ? S1f[4 + q] : S1f[q];
        float S2ij = S2f[q];
        float tij  = (1.0f / 3.0f) * S1i * S1j;
        const float* row = p0 + 8 + (jb + q) * 9;    // S2[j,:]
        float4 lo, hi4;
        float* lv = &lo.x; float* hv = &hi4.x;
#pragma unroll
        for (int k = 0; k < 8; ++k) {
            float val = S3f[q][k]
                      - 0.5f * (S1i * row[k] + S2ij * S1f[k])
                      + tij * S1f[k];
            if (k < 4) lv[k] = val; else hv[k - 4] = val;
        }
        float* dst = ob + 72 + 32 * s + 8 * q;
        *reinterpret_cast<float4*>(dst)     = lo;
        *reinterpret_cast<float4*>(dst + 4) = hi4;
    }
}

extern "C" void kernel_launch(void* const* d_in, const int* in_sizes, int n_in,
                              void* d_out, int out_size)
{
    const float* x = (const float*)d_in[0];
    float* out = (float*)d_out;
    (void)in_sizes; (void)n_in; (void)out_size;

    const int blocks = BATCH / BPB;   // 512
    logsig_kernel<<<blocks, TPB>>>(x, out);
}

// round 12
// speedup vs baseline: 1.2440x; 1.0708x over previous
#include <cuda_runtime.h>
#include <cstdint>

// Log-signature depth 3, d=8, L=256, B=2048.
// R11: R9 structure (smem-staged dx, packed f32x2 scan, 3 chunks of 85,
// Chen combine, aliased smem) with fine-grain blocks for load balance:
// TPB=96 (2 batches x 3 chunks), grid=1024, launch_bounds(96,8) -> 8
// blocks/SM, near-uniform 24 warps/SM. Per-step dj pair loaded directly
// via LDS.128 at offset jb (kills 4 SELs/step).

#define BATCH   2048
#define LPATH   256
#define DCH     8
#define OUT_PB  584
#define TPB     96             // 6 groups = 2 batches x 3 chunks
#define BPB     2
#define NCHUNK  3
#define CSTEPS  85             // 255 / 3
#define SIGSZ   656            // 8 + 8x9 (S2) + 64x9 (S3)
#define DXS     2052           // floats per batch dx region (8*256 + 4 pad)
#define SMEMF   4104           // 2*DXS; >= 6*SIGSZ = 3936 (sig aliases dx)

using u64 = unsigned long long;

__device__ __forceinline__ u64 pack2(float lo, float hi) {
    u64 r; asm("mov.b64 %0, {%1, %2};" : "=l"(r) : "f"(lo), "f"(hi)); return r;
}
__device__ __forceinline__ void unpack2(u64 v, float& lo, float& hi) {
    asm("mov.b64 {%0, %1}, %2;" : "=f"(lo), "=f"(hi) : "l"(v));
}
__device__ __forceinline__ u64 fma2(u64 a, u64 b, u64 c) {
    u64 d; asm("fma.rn.f32x2 %0, %1, %2, %3;" : "=l"(d) : "l"(a), "l"(b), "l"(c)); return d;
}

__global__ __launch_bounds__(TPB, 8)
void logsig_kernel(const float* __restrict__ x, float* __restrict__ out)
{
    __shared__ __align__(16) float smem[SMEMF];

    const int tid  = threadIdx.x;
    const int lane = tid & 31;
    const int s    = lane & 15;
    const int i    = s >> 1;
    const bool hib = (s & 1) != 0;
    const int jb   = hib ? 4 : 0;
    const unsigned gmask = 0xFFFFu << (lane & 16);

    const int gid   = tid >> 4;        // 0..5
    const int bL    = gid / NCHUNK;    // batch within block (0..1)
    const int chunk = gid - bL * NCHUNK;
    const long b = (long)blockIdx.x * BPB + bL;
    const int start = chunk * CSTEPS;

    // ---------------- phase 1: dx -> shared ----------------
    {
        const float4* xg = reinterpret_cast<const float4*>(
            x + (size_t)blockIdx.x * BPB * LPATH * DCH);
#pragma unroll
        for (int k = 0; k < 11; ++k) {
            int e = tid + TPB * k;          // (batch, point, half) in float4 units
            if (e < BPB * 512) {
                int bb = e >> 9;
                int r  = e & 511;
                int t  = r >> 1;
                int h  = r & 1;
                int tn = (t < 255) ? t + 1 : 255;   // dx[255] never read
                const float4* xb4 = xg + bb * 512;
                float4 cur = __ldg(xb4 + 2 * t  + h);
                float4 nxt = __ldg(xb4 + 2 * tn + h);
                float4 dv;
                dv.x = nxt.x - cur.x; dv.y = nxt.y - cur.y;
                dv.z = nxt.z - cur.z; dv.w = nxt.w - cur.w;
                *reinterpret_cast<float4*>(&smem[bb * DXS + t * 8 + h * 4]) = dv;
            }
        }
    }
    __syncthreads();

    // ---------------- phase 2: 85-step packed scan from smem -------------
    u64 S3p[4][4];
#pragma unroll
    for (int q = 0; q < 4; ++q)
#pragma unroll
        for (int kp = 0; kp < 4; ++kp) S3p[q][kp] = 0ull;
    u64 S2p0 = 0ull, S2p1 = 0ull;
    float S1i = 0.0f;

    const float* dxp = &smem[bL * DXS + start * 8];
    const longlong2* dv2 = reinterpret_cast<const longlong2*>(dxp);
    const longlong2* dj2 = reinterpret_cast<const longlong2*>(dxp + jb);

#pragma unroll 4
    for (int t = 0; t < CSTEPS; ++t) {
        longlong2 va = dv2[2 * t];
        longlong2 vb = dv2[2 * t + 1];
        longlong2 vj = dj2[2 * t];          // (dx_jb .. dx_jb+3) directly
        float dxi = dxp[t * 8 + i];

        u64 d0 = (u64)va.x, d1 = (u64)va.y, d2 = (u64)vb.x, d3 = (u64)vb.y;
        u64 dj01 = (u64)vj.x, dj23 = (u64)vj.y;

        float av = fmaf(dxi, 1.0f / 6.0f, 0.5f * S1i);   // old S1i
        float bv = fmaf(dxi, 0.5f, S1i);
        S1i += dxi;
        u64 a2 = pack2(av, av);
        u64 b2 = pack2(bv, bv);

        u64 m01 = fma2(a2, dj01, S2p0);                  // old S2
        u64 m23 = fma2(a2, dj23, S2p1);
        S2p0 = fma2(b2, dj01, S2p0);
        S2p1 = fma2(b2, dj23, S2p1);

        float m0, m1, m2, m3;
        unpack2(m01, m0, m1); unpack2(m23, m2, m3);
        u64 M0 = pack2(m0, m0), M1 = pack2(m1, m1);
        u64 M2 = pack2(m2, m2), M3 = pack2(m3, m3);

        S3p[0][0] = fma2(M0, d0, S3p[0][0]);
        S3p[0][1] = fma2(M0, d1, S3p[0][1]);
        S3p[0][2] = fma2(M0, d2, S3p[0][2]);
        S3p[0][3] = fma2(M0, d3, S3p[0][3]);
        S3p[1][0] = fma2(M1, d0, S3p[1][0]);
        S3p[1][1] = fma2(M1, d1, S3p[1][1]);
        S3p[1][2] = fma2(M1, d2, S3p[1][2]);
        S3p[1][3] = fma2(M1, d3, S3p[1][3]);
        S3p[2][0] = fma2(M2, d0, S3p[2][0]);
        S3p[2][1] = fma2(M2, d1, S3p[2][1]);
        S3p[2][2] = fma2(M2, d2, S3p[2][2]);
        S3p[2][3] = fma2(M2, d3, S3p[2][3]);
        S3p[3][0] = fma2(M3, d0, S3p[3][0]);
        S3p[3][1] = fma2(M3, d1, S3p[3][1]);
        S3p[3][2] = fma2(M3, d2, S3p[3][2]);
        S3p[3][3] = fma2(M3, d3, S3p[3][3]);
    }

    // ---- unpack scan state; S1 via telescoped endpoints (GMEM, L2-hot) --
    float S3f[4][8];
#pragma unroll
    for (int q = 0; q < 4; ++q)
#pragma unroll
        for (int kp = 0; kp < 4; ++kp)
            unpack2(S3p[q][kp], S3f[q][2 * kp], S3f[q][2 * kp + 1]);
    float S2f[4];
    unpack2(S2p0, S2f[0], S2f[1]);
    unpack2(S2p1, S2f[2], S2f[3]);

    float S1f[8];
    {
        const float4* xg2 = reinterpret_cast<const float4*>(
            x + (size_t)b * LPATH * DCH);
        int pend = start + CSTEPS;        // 85 / 170 / 255 — always in range
        float4 e0 = __ldg(xg2 + 2 * pend);
        float4 e1 = __ldg(xg2 + 2 * pend + 1);
        float4 s0 = __ldg(xg2 + 2 * start);
        float4 s1 = __ldg(xg2 + 2 * start + 1);
        S1f[0] = e0.x - s0.x; S1f[1] = e0.y - s0.y;
        S1f[2] = e0.z - s0.z; S1f[3] = e0.w - s0.w;
        S1f[4] = e1.x - s1.x; S1f[5] = e1.y - s1.y;
        S1f[6] = e1.z - s1.z; S1f[7] = e1.w - s1.w;
    }

    // ---------------- Chen combine (smem aliased over dx) ----------------
    __syncthreads();                       // dx buffer dead from here on
    float (*sig)[SIGSZ] = reinterpret_cast<float (*)[SIGSZ]>(smem);

    auto store_sig = [&](float* p) {
        if (s == 0) {
#pragma unroll
            for (int k = 0; k < 8; ++k) p[k] = S1f[k];
        }
#pragma unroll
        for (int q = 0; q < 4; ++q)
            p[8 + i * 9 + jb + q] = S2f[q];
#pragma unroll
        for (int q = 0; q < 4; ++q)
#pragma unroll
            for (int k = 0; k < 8; ++k)
                p[80 + (i * 8 + jb + q) * 9 + k] = S3f[q][k];
    };

    auto combine = [&](const float* p) {   // regs = earlier part a, p = later part b
        float S1b[8];
#pragma unroll
        for (int k = 0; k < 8; ++k) S1b[k] = p[k];
#pragma unroll
        for (int q = 0; q < 4; ++q) {
            const float* s2row = p + 8 + (jb + q) * 9;            // S2b[j,:]
            const float* s3row = p + 80 + (i * 8 + jb + q) * 9;   // S3b[i,j,:]
#pragma unroll
            for (int k = 0; k < 8; ++k)
                S3f[q][k] += S2f[q] * S1b[k] + S1i * s2row[k] + s3row[k];
            float S1bj = hib ? S1b[4 + q] : S1b[q];
            S2f[q] += S1i * S1bj + p[8 + i * 9 + jb + q];
        }
#pragma unroll
        for (int k = 0; k < 8; ++k) S1f[k] += S1b[k];
        S1i += p[i];
    };

    if (chunk != 0) store_sig(&sig[bL * NCHUNK + chunk][0]);
    __syncthreads();
    if (chunk != 0) return;

    combine(&sig[bL * NCHUNK + 1][0]);
    combine(&sig[bL * NCHUNK + 2][0]);

    // ---------------- log projection + writeback ----------------
    float* p0 = &sig[bL * NCHUNK + 0][0];
#pragma unroll
    for (int q = 0; q < 4; ++q)
        p0[8 + i * 9 + jb + q] = S2f[q];   // publish full S2 for [j,k] reads
    __syncwarp(gmask);

    float* ob = out + (size_t)b * OUT_PB;

    // l1
    if (s == 0) {
        *reinterpret_cast<float4*>(ob)     = make_float4(S1f[0], S1f[1], S1f[2], S1f[3]);
        *reinterpret_cast<float4*>(ob + 4) = make_float4(S1f[4], S1f[5], S1f[6], S1f[7]);
    }

    // l2 = S2 - 0.5 S1 x S1
    {
        float4 v; float* vv = &v.x;
#pragma unroll
        for (int q = 0; q < 4; ++q) {
            float S1j = hib ? S1f[4 + q] : S1f[q];
            vv[q] = S2f[q] - 0.5f * S1i * S1j;
        }
        *reinterpret_cast<float4*>(ob + 8 + 4 * s) = v;
    }

    // l3 = S3 - 0.5 (S1_i S2[j,k] + S2[i,j] S1_k) + (1/3) S1_i S1_j S1_k
#pragma unroll
    for (int q = 0; q < 4; ++q) {
        float S1j  = hib ? S1f[4 + q] : S1f[q];
        float S2ij = S2f[q];
        float tij  = (1.0f / 3.0f) * S1i * S1j;
        const float* row = p0 + 8 + (jb + q) * 9;    // S2[j,:]
        float4 lo, hi4;
        float* lv = &lo.x; float* hv = &hi4.x;
#pragma unroll
        for (int k = 0; k < 8; ++k) {
            float val = S3f[q][k]
                      - 0.5f * (S1i * row[k] + S2ij * S1f[k])
                      + tij * S1f[k];
            if (k < 4) lv[k] = val; else hv[k - 4] = val;
        }
        float* dst = ob + 72 + 32 * s + 8 * q;
        *reinterpret_cast<float4*>(dst)     = lo;
        *reinterpret_cast<float4*>(dst + 4) = hi4;
    }
}

extern "C" void kernel_launch(void* const* d_in, const int* in_sizes, int n_in,
                              void* d_out, int out_size)
{
    const float* x = (const float*)d_in[0];
    float* out = (float*)d_out;
    (void)in_sizes; (void)n_in; (void)out_size;

    const int blocks = BATCH / BPB;   // 1024
    logsig_kernel<<<blocks, TPB>>>(x, out);
}